// round 16
// baseline (speedup 1.0000x reference)
#include <cuda_runtime.h>
#include <cuda_fp16.h>
#include <cstdint>
#include <cfloat>

// Problem constants
#define BATCH   2
#define SEQ     2048
#define DMODEL  1024
#define NHEADS  16
#define HDIM    64
#define QKV_LD  3072
#define NTOK    (BATCH * SEQ)      // 4096
#define WINDOW  128
#define STRIDE  64

// Scratch (device globals: no allocation allowed) — fp16 dataflow
__device__ __half g_xh[(size_t)NTOK * DMODEL];      // x (half)
__device__ __half g_wqkvh[(size_t)DMODEL * QKV_LD]; // Wqkv (half)
__device__ __half g_wph[(size_t)DMODEL * DMODEL];   // Wproj (half)
__device__ __half g_qkvh[(size_t)NTOK * QKV_LD];    // qkv (half)
__device__ __half g_yh[(size_t)NTOK * DMODEL];      // y (half)

// pack two floats into half2 bits
__device__ __forceinline__ unsigned f2h2(float x, float y) {
    __half2 h = __float22half2_rn(make_float2(x, y));
    return *reinterpret_cast<unsigned*>(&h);
}
__device__ __forceinline__ uint2 h4(float4 v) {
    return make_uint2(f2h2(v.x, v.y), f2h2(v.z, v.w));
}
// Fast exp2 on the FMA pipe (x <= 0; clamped at -126). Rel err < 1e-4.
__device__ __forceinline__ float fexp2(float x) {
    x = fmaxf(x, -126.0f);
    float n = floorf(x);
    float f = x - n;
    float p = 0.00133336f;
    p = fmaf(p, f, 0.00961813f);
    p = fmaf(p, f, 0.05550411f);
    p = fmaf(p, f, 0.24022651f);
    p = fmaf(p, f, 0.69314718f);
    p = fmaf(p, f, 1.0f);
    return __int_as_float(((int)n + 127) << 23) * p;
}

// ---------------------------------------------------------------------------
// Fused fp32->fp16 convert for x, Wqkv, Wproj (ONE launch, ~50MB traffic).
// ---------------------------------------------------------------------------
__global__ __launch_bounds__(256) void cvt_all(
    const float4* __restrict__ a, uint2* __restrict__ oa, int na,
    const float4* __restrict__ b, uint2* __restrict__ ob, int nb,
    const float4* __restrict__ c, uint2* __restrict__ oc, int nc)
{
    const int total = na + nb + nc;
    for (int i = blockIdx.x * blockDim.x + threadIdx.x; i < total;
         i += gridDim.x * blockDim.x) {
        if (i < na)            oa[i]           = h4(a[i]);
        else if (i < na + nb)  ob[i - na]      = h4(b[i - na]);
        else                   oc[i - na - nb] = h4(c[i - na - nb]);
    }
}

// ===========================================================================
// FP16 mma.sync GEMM v3 (cp.async, BK=64): C[M,N] = A[M,K] @ B[K,N].
// CTA 128x128, BK=64, 256 threads = 8 warps (2M x 4N), warp tile 64x32.
// 3-stage cp.async ring (107.5KB smem), 2 CTAs/SM; 4 k16 steps per barrier
// (16 barriers per K=1024 GEMM, half of R15). Coalesced loaders (nL=4).
// A staged [m][k] pitch 72 halves (144B, conflict-free); B [k][n] pitch 136.
// ===========================================================================
#define BMh 128
#define BNh 128
#define BKh 64
#define APh 72     // A pitch (halves): 144B row stride
#define BPh 136    // B pitch (halves): 272B row stride
#define HSTAGES 3
#define HSTG_A (BMh * APh)   // 9216 halves
#define HSTG_B (BKh * BPh)   // 8704 halves
#define GEMM_SMEM (HSTAGES * (HSTG_A + HSTG_B) * (int)sizeof(__half))  // 107520

__device__ __forceinline__ void cp16h(uint32_t dst, const __half* src) {
    asm volatile("cp.async.ca.shared.global [%0], [%1], 16;"
                 :: "r"(dst), "l"(src) : "memory");
}

// 256-thread stage issue: A 128x64 halves (16KB), B 64x128 halves (16KB).
__device__ __forceinline__ void issue_stage_h(
    const __half* __restrict__ A, const __half* __restrict__ B,
    __half* As, __half* Bs, int row0, int col0, int k0, int tid, int N, int K)
{
    // A: 8 lanes/row (16B each, 128B row = 1 line), rows tid>>3 + 32p
    const int arow = tid >> 3;            // 0..31
    const int ach  = (tid & 7) * 8;       // 0..56
#pragma unroll
    for (int p = 0; p < 4; ++p) {
        const int r = arow + 32 * p;
        uint32_t d = (uint32_t)__cvta_generic_to_shared(&As[r * APh + ach]);
        cp16h(d, A + (size_t)(row0 + r) * K + k0 + ach);
    }
    // B: 16 lanes/row (256B row = 2 lines), rows tid>>4 + 16p
    const int brow = tid >> 4;            // 0..15
    const int bch  = (tid & 15) * 8;      // 0..120
#pragma unroll
    for (int p = 0; p < 4; ++p) {
        const int r = brow + 16 * p;
        uint32_t d = (uint32_t)__cvta_generic_to_shared(&Bs[r * BPh + bch]);
        cp16h(d, B + (size_t)(k0 + r) * N + col0 + bch);
    }
}

template<typename OutT>
__global__ __launch_bounds__(256, 2) void hgemm(
    const __half* __restrict__ A, const __half* __restrict__ B,
    OutT* __restrict__ C, int M, int N, int K)
{
    extern __shared__ __half smh[];
    __half* As0 = smh;                        // [HSTAGES][HSTG_A]
    __half* Bs0 = smh + HSTAGES * HSTG_A;     // [HSTAGES][HSTG_B]

    const int tid  = threadIdx.x;
    const int lane = tid & 31;
    const int wid  = tid >> 5;
    const int warp_m = wid >> 2;              // 0..1
    const int warp_n = wid & 3;               // 0..3
    const int row0 = blockIdx.y * BMh;
    const int col0 = blockIdx.x * BNh;

    float acc[4][4][4];
#pragma unroll
    for (int mi = 0; mi < 4; ++mi)
#pragma unroll
        for (int ni = 0; ni < 4; ++ni)
#pragma unroll
            for (int e = 0; e < 4; ++e) acc[mi][ni][e] = 0.0f;

    const int nk = K / BKh;

    // prologue: issue 2 stages
#pragma unroll
    for (int s = 0; s < HSTAGES - 1; ++s) {
        issue_stage_h(A, B, As0 + s * HSTG_A, Bs0 + s * HSTG_B,
                      row0, col0, s * BKh, tid, N, K);
        asm volatile("cp.async.commit_group;" ::: "memory");
    }

    const int lrow = lane & 15;
    const int lk8  = (lane & 16) ? 8 : 0;
    const int ln8  = (lane & 16) >> 1;

    int cur = 0;
    for (int it = 0; it < nk; ++it) {
        asm volatile("cp.async.wait_group 1;" ::: "memory");
        __syncthreads();

        if (it + HSTAGES - 1 < nk) {
            const int nb = (cur + HSTAGES - 1) % HSTAGES;
            issue_stage_h(A, B, As0 + nb * HSTG_A, Bs0 + nb * HSTG_B,
                          row0, col0, (it + HSTAGES - 1) * BKh, tid, N, K);
        }
        asm volatile("cp.async.commit_group;" ::: "memory");

        const __half* Ac = As0 + cur * HSTG_A;
        const __half* Bc = Bs0 + cur * HSTG_B;
        const unsigned smA = (unsigned)__cvta_generic_to_shared(Ac);
        const unsigned smB = (unsigned)__cvta_generic_to_shared(Bc);
#pragma unroll
        for (int ks = 0; ks < 4; ++ks) {
            unsigned a[4][4];
#pragma unroll
            for (int mi = 0; mi < 4; ++mi) {
                unsigned ad = smA +
                    (((warp_m * 64 + mi * 16 + lrow) * APh + ks * 16 + lk8) << 1);
                asm volatile(
                    "ldmatrix.sync.aligned.m8n8.x4.shared.b16 {%0,%1,%2,%3}, [%4];"
                    : "=r"(a[mi][0]), "=r"(a[mi][1]), "=r"(a[mi][2]), "=r"(a[mi][3])
                    : "r"(ad));
            }
            unsigned bf[2][4];
#pragma unroll
            for (int ng = 0; ng < 2; ++ng) {
                unsigned bd = smB +
                    (((ks * 16 + lrow) * BPh + warp_n * 32 + ng * 16 + ln8) << 1);
                asm volatile(
                    "ldmatrix.sync.aligned.m8n8.x4.trans.shared.b16 {%0,%1,%2,%3}, [%4];"
                    : "=r"(bf[ng][0]), "=r"(bf[ng][1]), "=r"(bf[ng][2]), "=r"(bf[ng][3])
                    : "r"(bd));
            }
#pragma unroll
            for (int mi = 0; mi < 4; ++mi)
#pragma unroll
                for (int ni = 0; ni < 4; ++ni) {
                    const unsigned b0 = bf[ni >> 1][(ni & 1) * 2];
                    const unsigned b1 = bf[ni >> 1][(ni & 1) * 2 + 1];
                    asm volatile(
                        "mma.sync.aligned.m16n8k16.row.col.f32.f16.f16.f32 "
                        "{%0,%1,%2,%3}, {%4,%5,%6,%7}, {%8,%9}, {%0,%1,%2,%3};"
                        : "+f"(acc[mi][ni][0]), "+f"(acc[mi][ni][1]),
                          "+f"(acc[mi][ni][2]), "+f"(acc[mi][ni][3])
                        : "r"(a[mi][0]), "r"(a[mi][1]), "r"(a[mi][2]), "r"(a[mi][3]),
                          "r"(b0), "r"(b1));
                }
        }

        cur = (cur + 1) % HSTAGES;
    }

    // ---- epilogue ----
    const int g  = lane >> 2;
    const int tg = lane & 3;
#pragma unroll
    for (int mi = 0; mi < 4; ++mi) {
#pragma unroll
        for (int ni = 0; ni < 4; ++ni) {
            const int row = row0 + warp_m * 64 + mi * 16 + g;
            const int col = col0 + warp_n * 32 + ni * 8 + 2 * tg;
            if constexpr (sizeof(OutT) == 2) {
                *(unsigned*)((__half*)C + (size_t)row * N + col) =
                    f2h2(acc[mi][ni][0], acc[mi][ni][1]);
                *(unsigned*)((__half*)C + (size_t)(row + 8) * N + col) =
                    f2h2(acc[mi][ni][2], acc[mi][ni][3]);
            } else {
                *(float2*)((float*)C + (size_t)row * N + col) =
                    make_float2(acc[mi][ni][0], acc[mi][ni][1]);
                *(float2*)((float*)C + (size_t)(row + 8) * N + col) =
                    make_float2(acc[mi][ni][2], acc[mi][ni][3]);
            }
        }
    }
}

// ===========================================================================
// FP16 tensor-core sparse flash attention (R15, unchanged — validated).
// ===========================================================================
#define P72 72
#define ATTN_SMEM (4 * 64 * P72 * (int)sizeof(__half))   // 36864 B
#define SC2 0.18033688f   // (1/sqrt(64)) * log2(e)

__global__ __launch_bounds__(128) void sparse_attn(
    const __half* __restrict__ qkvh, __half* __restrict__ yh)
{
    extern __shared__ __half smha[];
    __half* Qh = smha;               // [64 q][P72]
    __half* Kt = Qh + 64 * P72;      // [64 d][P72]   (K transposed)
    __half* Vh = Kt + 64 * P72;      // [64 key][P72]
    __half* Ph = Vh + 64 * P72;      // [64 q][P72]

    const int t    = blockIdx.x;
    const int h    = blockIdx.y;
    const int b    = blockIdx.z;
    const int tid  = threadIdx.x;
    const int lane = tid & 31;
    const int w    = tid >> 5;
    const int r0   = t * 64;

    const size_t base = (size_t)b * SEQ * QKV_LD;

    for (int e = tid; e < 1024; e += 128) {
        const int tok = e >> 4;
        const int d4  = (e & 15) * 4;
        *(uint2*)&Qh[tok * P72 + d4] =
            *(const uint2*)(qkvh + base + (size_t)(r0 + tok) * QKV_LD + h * HDIM + d4);
    }

    const int g  = lane >> 2;
    const int tg = lane & 3;
    const int lrow = lane & 15;
    const int lk8  = (lane & 16) ? 8 : 0;
    const int ln8  = (lane & 16) >> 1;

    float m0 = -3.0e38f, m1 = -3.0e38f, l0 = 0.0f, l1 = 0.0f;
    float o[8][4];
#pragma unroll
    for (int ni = 0; ni < 8; ++ni)
#pragma unroll
        for (int e = 0; e < 4; ++e) o[ni][e] = 0.0f;

    const int kb_start = (t >= 2) ? (t - 2) : 0;
    const int n_win    = t - kb_start + 1;
    const int nglob    = (t >= 3) ? (t - 2) : 0;
    const int n_tiles  = n_win + (nglob > 0 ? 1 : 0);

    const unsigned smQ = (unsigned)__cvta_generic_to_shared(Qh);
    const unsigned smK = (unsigned)__cvta_generic_to_shared(Kt);
    const unsigned smV = (unsigned)__cvta_generic_to_shared(Vh);
    const unsigned smP = (unsigned)__cvta_generic_to_shared(Ph);

    for (int it = 0; it < n_tiles; ++it) {
        const bool is_glob = (it == n_win);
        const int  kcol0   = (kb_start + it) * 64;

        __syncthreads();

        for (int e = tid; e < 1024; e += 128) {
            const int tok = e >> 4;
            const int d4  = (e & 15) * 4;
            int key;
            bool valid;
            if (is_glob) { key = tok * STRIDE; valid = (tok < nglob); }
            else         { key = kcol0 + tok;  valid = true; }
            uint2 kv, vv;
            if (valid) {
                const __half* kp = qkvh + base + (size_t)key * QKV_LD + DMODEL + h * HDIM + d4;
                kv = *(const uint2*)kp;
                vv = *(const uint2*)(kp + DMODEL);
            } else {
                kv = make_uint2(0u, 0u);
                vv = kv;
            }
            const __half2 k01 = *reinterpret_cast<__half2*>(&kv.x);
            const __half2 k23 = *reinterpret_cast<__half2*>(&kv.y);
            Kt[(d4 + 0) * P72 + tok] = __low2half(k01);
            Kt[(d4 + 1) * P72 + tok] = __high2half(k01);
            Kt[(d4 + 2) * P72 + tok] = __low2half(k23);
            Kt[(d4 + 3) * P72 + tok] = __high2half(k23);
            *(uint2*)&Vh[tok * P72 + d4] = vv;
        }
        __syncthreads();

        float s[8][4];
#pragma unroll
        for (int ni = 0; ni < 8; ++ni)
#pragma unroll
            for (int e = 0; e < 4; ++e) s[ni][e] = 0.0f;

#pragma unroll
        for (int ks = 0; ks < 4; ++ks) {
            unsigned a[4];
            unsigned ad = smQ + (((w * 16 + lrow) * P72 + ks * 16 + lk8) << 1);
            asm volatile(
                "ldmatrix.sync.aligned.m8n8.x4.shared.b16 {%0,%1,%2,%3}, [%4];"
                : "=r"(a[0]), "=r"(a[1]), "=r"(a[2]), "=r"(a[3]) : "r"(ad));
            unsigned bf[4][4];
#pragma unroll
            for (int ng = 0; ng < 4; ++ng) {
                unsigned bd = smK + (((ks * 16 + lrow) * P72 + ng * 16 + ln8) << 1);
                asm volatile(
                    "ldmatrix.sync.aligned.m8n8.x4.trans.shared.b16 {%0,%1,%2,%3}, [%4];"
                    : "=r"(bf[ng][0]), "=r"(bf[ng][1]), "=r"(bf[ng][2]), "=r"(bf[ng][3])
                    : "r"(bd));
            }
#pragma unroll
            for (int ni = 0; ni < 8; ++ni) {
                const unsigned b0 = bf[ni >> 1][(ni & 1) * 2];
                const unsigned b1 = bf[ni >> 1][(ni & 1) * 2 + 1];
                asm volatile(
                    "mma.sync.aligned.m16n8k16.row.col.f32.f16.f16.f32 "
                    "{%0,%1,%2,%3}, {%4,%5,%6,%7}, {%8,%9}, {%0,%1,%2,%3};"
                    : "+f"(s[ni][0]), "+f"(s[ni][1]), "+f"(s[ni][2]), "+f"(s[ni][3])
                    : "r"(a[0]), "r"(a[1]), "r"(a[2]), "r"(a[3]), "r"(b0), "r"(b1));
            }
        }

        const int row_lo = r0 + w * 16 + g;
        const int row_hi = row_lo + 8;
#pragma unroll
        for (int ni = 0; ni < 8; ++ni) {
            const int col0 = ni * 8 + 2 * tg;
#pragma unroll
            for (int e = 0; e < 4; ++e) {
                const int col = col0 + (e & 1);
                const int row = (e < 2) ? row_lo : row_hi;
                bool ok;
                if (is_glob) {
                    ok = col < nglob;
                } else {
                    const int c = kcol0 + col;
                    ok = (c <= row) && ((row - c) <= (WINDOW - 1) || (c & (STRIDE - 1)) == 0);
                }
                s[ni][e] = ok ? s[ni][e] * SC2 : -3.0e38f;
            }
        }

        float mx0 = -3.0e38f, mx1 = -3.0e38f;
#pragma unroll
        for (int ni = 0; ni < 8; ++ni) {
            mx0 = fmaxf(mx0, fmaxf(s[ni][0], s[ni][1]));
            mx1 = fmaxf(mx1, fmaxf(s[ni][2], s[ni][3]));
        }
        mx0 = fmaxf(mx0, __shfl_xor_sync(0xffffffffu, mx0, 1));
        mx0 = fmaxf(mx0, __shfl_xor_sync(0xffffffffu, mx0, 2));
        mx1 = fmaxf(mx1, __shfl_xor_sync(0xffffffffu, mx1, 1));
        mx1 = fmaxf(mx1, __shfl_xor_sync(0xffffffffu, mx1, 2));

        const float mn0 = fmaxf(m0, mx0);
        const float mn1 = fmaxf(m1, mx1);
        const float al0 = fexp2(m0 - mn0);
        const float al1 = fexp2(m1 - mn1);

        float rs0 = 0.0f, rs1 = 0.0f;
#pragma unroll
        for (int ni = 0; ni < 8; ++ni) {
            const int col0 = ni * 8 + 2 * tg;
            float p0 = fexp2(s[ni][0] - mn0);
            float p1 = fexp2(s[ni][1] - mn0);
            float p2 = fexp2(s[ni][2] - mn1);
            float p3 = fexp2(s[ni][3] - mn1);
            rs0 += p0 + p1;
            rs1 += p2 + p3;
            *(unsigned*)&Ph[(w * 16 + g) * P72 + col0]     = f2h2(p0, p1);
            *(unsigned*)&Ph[(w * 16 + g + 8) * P72 + col0] = f2h2(p2, p3);
        }
        rs0 += __shfl_xor_sync(0xffffffffu, rs0, 1);
        rs0 += __shfl_xor_sync(0xffffffffu, rs0, 2);
        rs1 += __shfl_xor_sync(0xffffffffu, rs1, 1);
        rs1 += __shfl_xor_sync(0xffffffffu, rs1, 2);

        l0 = l0 * al0 + rs0;
        l1 = l1 * al1 + rs1;
        m0 = mn0;
        m1 = mn1;
#pragma unroll
        for (int ni = 0; ni < 8; ++ni) {
            o[ni][0] *= al0;
            o[ni][1] *= al0;
            o[ni][2] *= al1;
            o[ni][3] *= al1;
        }
        __syncwarp();

#pragma unroll
        for (int ks = 0; ks < 4; ++ks) {
            unsigned a[4];
            unsigned ad = smP + (((w * 16 + lrow) * P72 + ks * 16 + lk8) << 1);
            asm volatile(
                "ldmatrix.sync.aligned.m8n8.x4.shared.b16 {%0,%1,%2,%3}, [%4];"
                : "=r"(a[0]), "=r"(a[1]), "=r"(a[2]), "=r"(a[3]) : "r"(ad));
            unsigned bf[4][4];
#pragma unroll
            for (int ng = 0; ng < 4; ++ng) {
                unsigned bd = smV + (((ks * 16 + lrow) * P72 + ng * 16 + ln8) << 1);
                asm volatile(
                    "ldmatrix.sync.aligned.m8n8.x4.trans.shared.b16 {%0,%1,%2,%3}, [%4];"
                    : "=r"(bf[ng][0]), "=r"(bf[ng][1]), "=r"(bf[ng][2]), "=r"(bf[ng][3])
                    : "r"(bd));
            }
#pragma unroll
            for (int ni = 0; ni < 8; ++ni) {
                const unsigned b0 = bf[ni >> 1][(ni & 1) * 2];
                const unsigned b1 = bf[ni >> 1][(ni & 1) * 2 + 1];
                asm volatile(
                    "mma.sync.aligned.m16n8k16.row.col.f32.f16.f16.f32 "
                    "{%0,%1,%2,%3}, {%4,%5,%6,%7}, {%8,%9}, {%0,%1,%2,%3};"
                    : "+f"(o[ni][0]), "+f"(o[ni][1]), "+f"(o[ni][2]), "+f"(o[ni][3])
                    : "r"(a[0]), "r"(a[1]), "r"(a[2]), "r"(a[3]), "r"(b0), "r"(b1));
            }
        }
        __syncwarp();
    }

    const float inv0 = 1.0f / l0;
    const float inv1 = 1.0f / l1;
    const size_t row_lo = (size_t)b * SEQ + r0 + w * 16 + g;
#pragma unroll
    for (int ni = 0; ni < 8; ++ni) {
        const int col = h * HDIM + ni * 8 + 2 * tg;
        *(unsigned*)&yh[row_lo * DMODEL + col] =
            f2h2(o[ni][0] * inv0, o[ni][1] * inv0);
        *(unsigned*)&yh[(row_lo + 8) * DMODEL + col] =
            f2h2(o[ni][2] * inv1, o[ni][3] * inv1);
    }
}

// ---------------------------------------------------------------------------
extern "C" void kernel_launch(void* const* d_in, const int* in_sizes, int n_in,
                              void* d_out, int out_size)
{
    const float* x     = (const float*)d_in[0];
    const float* Wqkv  = (const float*)d_in[1];
    const float* Wproj = (const float*)d_in[2];
    float* out = (float*)d_out;

    __half *xh = nullptr, *wqkvh = nullptr, *wph = nullptr, *qkvh = nullptr, *yh = nullptr;
    cudaGetSymbolAddress((void**)&xh, g_xh);
    cudaGetSymbolAddress((void**)&wqkvh, g_wqkvh);
    cudaGetSymbolAddress((void**)&wph, g_wph);
    cudaGetSymbolAddress((void**)&qkvh, g_qkvh);
    cudaGetSymbolAddress((void**)&yh, g_yh);

    cudaFuncSetAttribute(hgemm<__half>, cudaFuncAttributeMaxDynamicSharedMemorySize, GEMM_SMEM);
    cudaFuncSetAttribute(hgemm<float>,  cudaFuncAttributeMaxDynamicSharedMemorySize, GEMM_SMEM);
    cudaFuncSetAttribute(sparse_attn,   cudaFuncAttributeMaxDynamicSharedMemorySize, ATTN_SMEM);

    // 0) fp32 -> fp16 convert (one kernel)
    cvt_all<<<2048, 256>>>(
        (const float4*)x,     (uint2*)xh,    NTOK * DMODEL / 4,
        (const float4*)Wqkv,  (uint2*)wqkvh, DMODEL * QKV_LD / 4,
        (const float4*)Wproj, (uint2*)wph,   DMODEL * DMODEL / 4);

    // 1) QKV projection: [4096,1024] @ [1024,3072] -> half qkv
    hgemm<__half><<<dim3(QKV_LD / BNh, NTOK / BMh), 256, GEMM_SMEM>>>(
        xh, wqkvh, qkvh, NTOK, QKV_LD, DMODEL);

    // 2) Sparse attention (fp16 tensor cores) -> half y
    sparse_attn<<<dim3(SEQ / 64, NHEADS, BATCH), 128, ATTN_SMEM>>>(qkvh, yh);

    // 3) Output projection: [4096,1024] @ [1024,1024] -> fp32 out
    hgemm<float><<<dim3(DMODEL / BNh, NTOK / BMh), 256, GEMM_SMEM>>>(
        yh, wph, out, NTOK, DMODEL, DMODEL);
}

// round 17
// speedup vs baseline: 1.0965x; 1.0965x over previous
#include <cuda_runtime.h>
#include <cuda_fp16.h>
#include <cstdint>
#include <cfloat>

// Problem constants
#define BATCH   2
#define SEQ     2048
#define DMODEL  1024
#define NHEADS  16
#define HDIM    64
#define QKV_LD  3072
#define NTOK    (BATCH * SEQ)      // 4096
#define WINDOW  128
#define STRIDE  64

// Scratch (device globals: no allocation allowed) — fp16 dataflow
__device__ __half g_xh[(size_t)NTOK * DMODEL];      // x (half)
__device__ __half g_wqkvh[(size_t)DMODEL * QKV_LD]; // Wqkv (half)
__device__ __half g_wph[(size_t)DMODEL * DMODEL];   // Wproj (half)
__device__ __half g_qkvh[(size_t)NTOK * QKV_LD];    // qkv (half)
__device__ __half g_yh[(size_t)NTOK * DMODEL];      // y (half)

// pack two floats into half2 bits
__device__ __forceinline__ unsigned f2h2(float x, float y) {
    __half2 h = __float22half2_rn(make_float2(x, y));
    return *reinterpret_cast<unsigned*>(&h);
}
__device__ __forceinline__ uint2 h4(float4 v) {
    return make_uint2(f2h2(v.x, v.y), f2h2(v.z, v.w));
}
// Fast exp2 on the FMA pipe (x <= 0; clamped at -126). Rel err < 1e-4.
__device__ __forceinline__ float fexp2(float x) {
    x = fmaxf(x, -126.0f);
    float n = floorf(x);
    float f = x - n;
    float p = 0.00133336f;
    p = fmaf(p, f, 0.00961813f);
    p = fmaf(p, f, 0.05550411f);
    p = fmaf(p, f, 0.24022651f);
    p = fmaf(p, f, 0.69314718f);
    p = fmaf(p, f, 1.0f);
    return __int_as_float(((int)n + 127) << 23) * p;
}

__device__ __forceinline__ void cp16h(uint32_t dst, const __half* src) {
    asm volatile("cp.async.ca.shared.global [%0], [%1], 16;"
                 :: "r"(dst), "l"(src) : "memory");
}

// ---------------------------------------------------------------------------
// Fused fp32->fp16 convert for x, Wqkv, Wproj (ONE launch).
// ---------------------------------------------------------------------------
__global__ __launch_bounds__(256) void cvt_all(
    const float4* __restrict__ a, uint2* __restrict__ oa, int na,
    const float4* __restrict__ b, uint2* __restrict__ ob, int nb,
    const float4* __restrict__ c, uint2* __restrict__ oc, int nc)
{
    const int total = na + nb + nc;
    for (int i = blockIdx.x * blockDim.x + threadIdx.x; i < total;
         i += gridDim.x * blockDim.x) {
        if (i < na)            oa[i]           = h4(a[i]);
        else if (i < na + nb)  ob[i - na]      = h4(b[i - na]);
        else                   oc[i - na - nb] = h4(c[i - na - nb]);
    }
}

// ===========================================================================
// FP16 mma.sync GEMM (R15 config verbatim — best measured GEMM).
// CTA 128x128, BK=32, 256 threads = 8 warps (2M x 4N), warp tile 64x32.
// 4-stage cp.async ring, 2 CTAs/SM.
// ===========================================================================
#define BMh 128
#define BNh 128
#define BKh 32
#define APh 40     // A pitch (halves): 80B row stride
#define BPh 136    // B pitch (halves): 272B row stride
#define HSTAGES 4
#define HSTG_A (BMh * APh)   // 5120 halves
#define HSTG_B (BKh * BPh)   // 4352 halves
#define GEMM_SMEM (HSTAGES * (HSTG_A + HSTG_B) * (int)sizeof(__half))  // 75776

__device__ __forceinline__ void issue_stage_h(
    const __half* __restrict__ A, const __half* __restrict__ B,
    __half* As, __half* Bs, int row0, int col0, int k0, int tid, int N, int K)
{
    const int arow = tid >> 2;            // 0..63
    const int ach  = (tid & 3) * 8;       // 0,8,16,24
#pragma unroll
    for (int p = 0; p < 2; ++p) {
        const int r = arow + 64 * p;
        uint32_t d = (uint32_t)__cvta_generic_to_shared(&As[r * APh + ach]);
        cp16h(d, A + (size_t)(row0 + r) * K + k0 + ach);
    }
    const int brow = tid >> 4;            // 0..15
    const int bch  = (tid & 15) * 8;      // 0..120
#pragma unroll
    for (int p = 0; p < 2; ++p) {
        const int r = brow + 16 * p;
        uint32_t d = (uint32_t)__cvta_generic_to_shared(&Bs[r * BPh + bch]);
        cp16h(d, B + (size_t)(k0 + r) * N + col0 + bch);
    }
}

template<typename OutT>
__global__ __launch_bounds__(256, 2) void hgemm(
    const __half* __restrict__ A, const __half* __restrict__ B,
    OutT* __restrict__ C, int M, int N, int K)
{
    extern __shared__ __half smh[];
    __half* As0 = smh;                        // [HSTAGES][HSTG_A]
    __half* Bs0 = smh + HSTAGES * HSTG_A;     // [HSTAGES][HSTG_B]

    const int tid  = threadIdx.x;
    const int lane = tid & 31;
    const int wid  = tid >> 5;
    const int warp_m = wid >> 2;              // 0..1
    const int warp_n = wid & 3;               // 0..3
    const int row0 = blockIdx.y * BMh;
    const int col0 = blockIdx.x * BNh;

    float acc[4][4][4];
#pragma unroll
    for (int mi = 0; mi < 4; ++mi)
#pragma unroll
        for (int ni = 0; ni < 4; ++ni)
#pragma unroll
            for (int e = 0; e < 4; ++e) acc[mi][ni][e] = 0.0f;

    const int nk = K / BKh;

#pragma unroll
    for (int s = 0; s < HSTAGES - 1; ++s) {
        issue_stage_h(A, B, As0 + s * HSTG_A, Bs0 + s * HSTG_B,
                      row0, col0, s * BKh, tid, N, K);
        asm volatile("cp.async.commit_group;" ::: "memory");
    }

    const int lrow = lane & 15;
    const int lk8  = (lane & 16) ? 8 : 0;
    const int ln8  = (lane & 16) >> 1;

    for (int it = 0; it < nk; ++it) {
        const int cur = it & (HSTAGES - 1);

        asm volatile("cp.async.wait_group 2;" ::: "memory");
        __syncthreads();

        if (it + HSTAGES - 1 < nk) {
            const int nb = (it + HSTAGES - 1) & (HSTAGES - 1);
            issue_stage_h(A, B, As0 + nb * HSTG_A, Bs0 + nb * HSTG_B,
                          row0, col0, (it + HSTAGES - 1) * BKh, tid, N, K);
        }
        asm volatile("cp.async.commit_group;" ::: "memory");

        const __half* Ac = As0 + cur * HSTG_A;
        const __half* Bc = Bs0 + cur * HSTG_B;
        const unsigned smA = (unsigned)__cvta_generic_to_shared(Ac);
        const unsigned smB = (unsigned)__cvta_generic_to_shared(Bc);
#pragma unroll
        for (int ks = 0; ks < 2; ++ks) {
            unsigned a[4][4];
#pragma unroll
            for (int mi = 0; mi < 4; ++mi) {
                unsigned ad = smA +
                    (((warp_m * 64 + mi * 16 + lrow) * APh + ks * 16 + lk8) << 1);
                asm volatile(
                    "ldmatrix.sync.aligned.m8n8.x4.shared.b16 {%0,%1,%2,%3}, [%4];"
                    : "=r"(a[mi][0]), "=r"(a[mi][1]), "=r"(a[mi][2]), "=r"(a[mi][3])
                    : "r"(ad));
            }
            unsigned bf[2][4];
#pragma unroll
            for (int ng = 0; ng < 2; ++ng) {
                unsigned bd = smB +
                    (((ks * 16 + lrow) * BPh + warp_n * 32 + ng * 16 + ln8) << 1);
                asm volatile(
                    "ldmatrix.sync.aligned.m8n8.x4.trans.shared.b16 {%0,%1,%2,%3}, [%4];"
                    : "=r"(bf[ng][0]), "=r"(bf[ng][1]), "=r"(bf[ng][2]), "=r"(bf[ng][3])
                    : "r"(bd));
            }
#pragma unroll
            for (int mi = 0; mi < 4; ++mi)
#pragma unroll
                for (int ni = 0; ni < 4; ++ni) {
                    const unsigned b0 = bf[ni >> 1][(ni & 1) * 2];
                    const unsigned b1 = bf[ni >> 1][(ni & 1) * 2 + 1];
                    asm volatile(
                        "mma.sync.aligned.m16n8k16.row.col.f32.f16.f16.f32 "
                        "{%0,%1,%2,%3}, {%4,%5,%6,%7}, {%8,%9}, {%0,%1,%2,%3};"
                        : "+f"(acc[mi][ni][0]), "+f"(acc[mi][ni][1]),
                          "+f"(acc[mi][ni][2]), "+f"(acc[mi][ni][3])
                        : "r"(a[mi][0]), "r"(a[mi][1]), "r"(a[mi][2]), "r"(a[mi][3]),
                          "r"(b0), "r"(b1));
                }
        }
    }

    const int g  = lane >> 2;
    const int tg = lane & 3;
#pragma unroll
    for (int mi = 0; mi < 4; ++mi) {
#pragma unroll
        for (int ni = 0; ni < 4; ++ni) {
            const int row = row0 + warp_m * 64 + mi * 16 + g;
            const int col = col0 + warp_n * 32 + ni * 8 + 2 * tg;
            if constexpr (sizeof(OutT) == 2) {
                *(unsigned*)((__half*)C + (size_t)row * N + col) =
                    f2h2(acc[mi][ni][0], acc[mi][ni][1]);
                *(unsigned*)((__half*)C + (size_t)(row + 8) * N + col) =
                    f2h2(acc[mi][ni][2], acc[mi][ni][3]);
            } else {
                *(float2*)((float*)C + (size_t)row * N + col) =
                    make_float2(acc[mi][ni][0], acc[mi][ni][1]);
                *(float2*)((float*)C + (size_t)(row + 8) * N + col) =
                    make_float2(acc[mi][ni][2], acc[mi][ni][3]);
            }
        }
    }
}

// ===========================================================================
// FP16 sparse flash attention v2 (R17): cp.async double-buffered K/V staging,
// K/V both in NATURAL [key][d] layout (no transpose scatter).
// S = Q K^T: B operand = [key][d] via NON-trans ldmatrix
//   (lane map: row = ng*16 + (l&7) + ((l&16)>>1), col = ks*16 + (l&8);
//    matrices 0..3 = (n8 x k8) blocks in b0/b1 order).
// O += P V: B operand via trans ldmatrix on natural V (as R15).
// Smem: Q + P + 2x(K+V) = 6 x 64 x 72 halves = 55296 B -> 4 CTAs/SM.
// ===========================================================================
#define PA 72
#define ATTN_SMEM (6 * 64 * PA * (int)sizeof(__half))   // 55296 B
#define SC2 0.18033688f   // (1/sqrt(64)) * log2(e)

// Stage one K/V tile (natural layout) via cp.async; invalid rows zeroed by STS.
__device__ __forceinline__ void stage_kv(
    const __half* __restrict__ qkvh, size_t base, int h,
    __half* K, __half* V, int kcol0, bool is_glob, int nglob, int tid)
{
#pragma unroll
    for (int p = 0; p < 4; ++p) {
        const int e   = tid + p * 128;    // 0..511
        const int tok = e >> 3;           // 0..63
        const int c8  = (e & 7) * 8;      // 0..56 halves
        int key;
        bool valid;
        if (is_glob) { key = tok * STRIDE; valid = (tok < nglob); }
        else         { key = kcol0 + tok;  valid = true; }
        uint32_t dk = (uint32_t)__cvta_generic_to_shared(&K[tok * PA + c8]);
        uint32_t dv = (uint32_t)__cvta_generic_to_shared(&V[tok * PA + c8]);
        if (valid) {
            const __half* kp = qkvh + base + (size_t)key * QKV_LD + DMODEL + h * HDIM + c8;
            cp16h(dk, kp);
            cp16h(dv, kp + DMODEL);
        } else {
            *(uint4*)&K[tok * PA + c8] = make_uint4(0u, 0u, 0u, 0u);
            *(uint4*)&V[tok * PA + c8] = make_uint4(0u, 0u, 0u, 0u);
        }
    }
}

__global__ __launch_bounds__(128) void sparse_attn(
    const __half* __restrict__ qkvh, __half* __restrict__ yh)
{
    extern __shared__ __half smha[];
    __half* Qh  = smha;                  // [64 q][PA]
    __half* Ph  = Qh + 64 * PA;          // [64 q][PA]
    __half* KV0 = Ph + 64 * PA;          // K(i) = KV0 + i*2*64*PA, V(i) = K(i)+64*PA

    const int t    = blockIdx.x;
    const int h    = blockIdx.y;
    const int b    = blockIdx.z;
    const int tid  = threadIdx.x;
    const int lane = tid & 31;
    const int w    = tid >> 5;
    const int r0   = t * 64;

    const size_t base = (size_t)b * SEQ * QKV_LD;

    const int kb_start = (t >= 2) ? (t - 2) : 0;
    const int n_win    = t - kb_start + 1;
    const int nglob    = (t >= 3) ? (t - 2) : 0;
    const int n_tiles  = n_win + (nglob > 0 ? 1 : 0);

    // ---- prologue: Q (cp.async) + tile 0 K/V, one commit group ----
#pragma unroll
    for (int p = 0; p < 4; ++p) {
        const int e   = tid + p * 128;
        const int tok = e >> 3;
        const int c8  = (e & 7) * 8;
        uint32_t dq = (uint32_t)__cvta_generic_to_shared(&Qh[tok * PA + c8]);
        cp16h(dq, qkvh + base + (size_t)(r0 + tok) * QKV_LD + h * HDIM + c8);
    }
    stage_kv(qkvh, base, h, KV0, KV0 + 64 * PA,
             kb_start * 64, (0 == n_win), nglob, tid);
    asm volatile("cp.async.commit_group;" ::: "memory");

    const int g  = lane >> 2;
    const int tg = lane & 3;
    const int lrow = lane & 15;
    const int lk8  = (lane & 16) ? 8 : 0;
    const int ln8  = (lane & 16) >> 1;
    // non-trans B-frag addressing (S phase)
    const int krow_off = (lane & 7) + ((lane & 16) >> 1);   // row within n16 group
    const int kcol_off = (lane & 8);                        // k8 selector

    float m0 = -3.0e38f, m1 = -3.0e38f, l0 = 0.0f, l1 = 0.0f;
    float o[8][4];
#pragma unroll
    for (int ni = 0; ni < 8; ++ni)
#pragma unroll
        for (int e = 0; e < 4; ++e) o[ni][e] = 0.0f;

    const unsigned smQ = (unsigned)__cvta_generic_to_shared(Qh);
    const unsigned smP = (unsigned)__cvta_generic_to_shared(Ph);

    for (int it = 0; it < n_tiles; ++it) {
        const bool is_glob = (it == n_win);
        const int  kcol0   = (kb_start + it) * 64;
        __half* Kc = KV0 + (it & 1) * 2 * 64 * PA;
        __half* Vc = Kc + 64 * PA;

        __syncthreads();   // WAR: prior compute on buffer (it+1)&1 finished

        if (it + 1 < n_tiles) {
            __half* Kn = KV0 + ((it + 1) & 1) * 2 * 64 * PA;
            stage_kv(qkvh, base, h, Kn, Kn + 64 * PA,
                     (kb_start + it + 1) * 64, (it + 1 == n_win), nglob, tid);
        }
        asm volatile("cp.async.commit_group;" ::: "memory");
        if (it + 1 < n_tiles)
            asm volatile("cp.async.wait_group 1;" ::: "memory");
        else
            asm volatile("cp.async.wait_group 0;" ::: "memory");
        __syncthreads();   // visibility of tile it across warps

        const unsigned smK = (unsigned)__cvta_generic_to_shared(Kc);
        const unsigned smV = (unsigned)__cvta_generic_to_shared(Vc);

        // ---- S = Q K^T (fp16 mma, 4 k16 steps; B via non-trans ldmatrix) ----
        float s[8][4];
#pragma unroll
        for (int ni = 0; ni < 8; ++ni)
#pragma unroll
            for (int e = 0; e < 4; ++e) s[ni][e] = 0.0f;

#pragma unroll
        for (int ks = 0; ks < 4; ++ks) {
            unsigned a[4];
            unsigned ad = smQ + (((w * 16 + lrow) * PA + ks * 16 + lk8) << 1);
            asm volatile(
                "ldmatrix.sync.aligned.m8n8.x4.shared.b16 {%0,%1,%2,%3}, [%4];"
                : "=r"(a[0]), "=r"(a[1]), "=r"(a[2]), "=r"(a[3]) : "r"(ad));
            unsigned bf[4][4];
#pragma unroll
            for (int ng = 0; ng < 4; ++ng) {
                unsigned bd = smK +
                    (((ng * 16 + krow_off) * PA + ks * 16 + kcol_off) << 1);
                asm volatile(
                    "ldmatrix.sync.aligned.m8n8.x4.shared.b16 {%0,%1,%2,%3}, [%4];"
                    : "=r"(bf[ng][0]), "=r"(bf[ng][1]), "=r"(bf[ng][2]), "=r"(bf[ng][3])
                    : "r"(bd));
            }
#pragma unroll
            for (int ni = 0; ni < 8; ++ni) {
                const unsigned b0 = bf[ni >> 1][(ni & 1) * 2];
                const unsigned b1 = bf[ni >> 1][(ni & 1) * 2 + 1];
                asm volatile(
                    "mma.sync.aligned.m16n8k16.row.col.f32.f16.f16.f32 "
                    "{%0,%1,%2,%3}, {%4,%5,%6,%7}, {%8,%9}, {%0,%1,%2,%3};"
                    : "+f"(s[ni][0]), "+f"(s[ni][1]), "+f"(s[ni][2]), "+f"(s[ni][3])
                    : "r"(a[0]), "r"(a[1]), "r"(a[2]), "r"(a[3]), "r"(b0), "r"(b1));
            }
        }

        // ---- mask + scale (base-2 domain) ----
        const int row_lo = r0 + w * 16 + g;
        const int row_hi = row_lo + 8;
#pragma unroll
        for (int ni = 0; ni < 8; ++ni) {
            const int col0 = ni * 8 + 2 * tg;
#pragma unroll
            for (int e = 0; e < 4; ++e) {
                const int col = col0 + (e & 1);
                const int row = (e < 2) ? row_lo : row_hi;
                bool ok;
                if (is_glob) {
                    ok = col < nglob;
                } else {
                    const int c = kcol0 + col;
                    ok = (c <= row) && ((row - c) <= (WINDOW - 1) || (c & (STRIDE - 1)) == 0);
                }
                s[ni][e] = ok ? s[ni][e] * SC2 : -3.0e38f;
            }
        }

        // ---- online softmax ----
        float mx0 = -3.0e38f, mx1 = -3.0e38f;
#pragma unroll
        for (int ni = 0; ni < 8; ++ni) {
            mx0 = fmaxf(mx0, fmaxf(s[ni][0], s[ni][1]));
            mx1 = fmaxf(mx1, fmaxf(s[ni][2], s[ni][3]));
        }
        mx0 = fmaxf(mx0, __shfl_xor_sync(0xffffffffu, mx0, 1));
        mx0 = fmaxf(mx0, __shfl_xor_sync(0xffffffffu, mx0, 2));
        mx1 = fmaxf(mx1, __shfl_xor_sync(0xffffffffu, mx1, 1));
        mx1 = fmaxf(mx1, __shfl_xor_sync(0xffffffffu, mx1, 2));

        const float mn0 = fmaxf(m0, mx0);
        const float mn1 = fmaxf(m1, mx1);
        const float al0 = fexp2(m0 - mn0);
        const float al1 = fexp2(m1 - mn1);

        float rs0 = 0.0f, rs1 = 0.0f;
#pragma unroll
        for (int ni = 0; ni < 8; ++ni) {
            const int col0 = ni * 8 + 2 * tg;
            float p0 = fexp2(s[ni][0] - mn0);
            float p1 = fexp2(s[ni][1] - mn0);
            float p2 = fexp2(s[ni][2] - mn1);
            float p3 = fexp2(s[ni][3] - mn1);
            rs0 += p0 + p1;
            rs1 += p2 + p3;
            *(unsigned*)&Ph[(w * 16 + g) * PA + col0]     = f2h2(p0, p1);
            *(unsigned*)&Ph[(w * 16 + g + 8) * PA + col0] = f2h2(p2, p3);
        }
        rs0 += __shfl_xor_sync(0xffffffffu, rs0, 1);
        rs0 += __shfl_xor_sync(0xffffffffu, rs0, 2);
        rs1 += __shfl_xor_sync(0xffffffffu, rs1, 1);
        rs1 += __shfl_xor_sync(0xffffffffu, rs1, 2);

        l0 = l0 * al0 + rs0;
        l1 = l1 * al1 + rs1;
        m0 = mn0;
        m1 = mn1;
#pragma unroll
        for (int ni = 0; ni < 8; ++ni) {
            o[ni][0] *= al0;
            o[ni][1] *= al0;
            o[ni][2] *= al1;
            o[ni][3] *= al1;
        }
        __syncwarp();

        // ---- O += P V (fp16 mma; B via trans ldmatrix on natural V) ----
#pragma unroll
        for (int ks = 0; ks < 4; ++ks) {
            unsigned a[4];
            unsigned ad = smP + (((w * 16 + lrow) * PA + ks * 16 + lk8) << 1);
            asm volatile(
                "ldmatrix.sync.aligned.m8n8.x4.shared.b16 {%0,%1,%2,%3}, [%4];"
                : "=r"(a[0]), "=r"(a[1]), "=r"(a[2]), "=r"(a[3]) : "r"(ad));
            unsigned bf[4][4];
#pragma unroll
            for (int ng = 0; ng < 4; ++ng) {
                unsigned bd = smV + (((ks * 16 + lrow) * PA + ng * 16 + ln8) << 1);
                asm volatile(
                    "ldmatrix.sync.aligned.m8n8.x4.trans.shared.b16 {%0,%1,%2,%3}, [%4];"
                    : "=r"(bf[ng][0]), "=r"(bf[ng][1]), "=r"(bf[ng][2]), "=r"(bf[ng][3])
                    : "r"(bd));
            }
#pragma unroll
            for (int ni = 0; ni < 8; ++ni) {
                const unsigned b0 = bf[ni >> 1][(ni & 1) * 2];
                const unsigned b1 = bf[ni >> 1][(ni & 1) * 2 + 1];
                asm volatile(
                    "mma.sync.aligned.m16n8k16.row.col.f32.f16.f16.f32 "
                    "{%0,%1,%2,%3}, {%4,%5,%6,%7}, {%8,%9}, {%0,%1,%2,%3};"
                    : "+f"(o[ni][0]), "+f"(o[ni][1]), "+f"(o[ni][2]), "+f"(o[ni][3])
                    : "r"(a[0]), "r"(a[1]), "r"(a[2]), "r"(a[3]), "r"(b0), "r"(b1));
            }
        }
        __syncwarp();
    }

    // ---- epilogue: normalize + write y (half) ----
    const float inv0 = 1.0f / l0;
    const float inv1 = 1.0f / l1;
    const size_t row_lo = (size_t)b * SEQ + r0 + w * 16 + g;
#pragma unroll
    for (int ni = 0; ni < 8; ++ni) {
        const int col = h * HDIM + ni * 8 + 2 * tg;
        *(unsigned*)&yh[row_lo * DMODEL + col] =
            f2h2(o[ni][0] * inv0, o[ni][1] * inv0);
        *(unsigned*)&yh[(row_lo + 8) * DMODEL + col] =
            f2h2(o[ni][2] * inv1, o[ni][3] * inv1);
    }
}

// ---------------------------------------------------------------------------
extern "C" void kernel_launch(void* const* d_in, const int* in_sizes, int n_in,
                              void* d_out, int out_size)
{
    const float* x     = (const float*)d_in[0];
    const float* Wqkv  = (const float*)d_in[1];
    const float* Wproj = (const float*)d_in[2];
    float* out = (float*)d_out;

    __half *xh = nullptr, *wqkvh = nullptr, *wph = nullptr, *qkvh = nullptr, *yh = nullptr;
    cudaGetSymbolAddress((void**)&xh, g_xh);
    cudaGetSymbolAddress((void**)&wqkvh, g_wqkvh);
    cudaGetSymbolAddress((void**)&wph, g_wph);
    cudaGetSymbolAddress((void**)&qkvh, g_qkvh);
    cudaGetSymbolAddress((void**)&yh, g_yh);

    cudaFuncSetAttribute(hgemm<__half>, cudaFuncAttributeMaxDynamicSharedMemorySize, GEMM_SMEM);
    cudaFuncSetAttribute(hgemm<float>,  cudaFuncAttributeMaxDynamicSharedMemorySize, GEMM_SMEM);
    cudaFuncSetAttribute(sparse_attn,   cudaFuncAttributeMaxDynamicSharedMemorySize, ATTN_SMEM);

    // 0) fp32 -> fp16 convert (one kernel)
    cvt_all<<<2048, 256>>>(
        (const float4*)x,     (uint2*)xh,    NTOK * DMODEL / 4,
        (const float4*)Wqkv,  (uint2*)wqkvh, DMODEL * QKV_LD / 4,
        (const float4*)Wproj, (uint2*)wph,   DMODEL * DMODEL / 4);

    // 1) QKV projection: [4096,1024] @ [1024,3072] -> half qkv
    hgemm<__half><<<dim3(QKV_LD / BNh, NTOK / BMh), 256, GEMM_SMEM>>>(
        xh, wqkvh, qkvh, NTOK, QKV_LD, DMODEL);

    // 2) Sparse attention (fp16 tensor cores, pipelined staging) -> half y
    sparse_attn<<<dim3(SEQ / 64, NHEADS, BATCH), 128, ATTN_SMEM>>>(qkvh, yh);

    // 3) Output projection: [4096,1024] @ [1024,1024] -> fp32 out
    hgemm<float><<<dim3(DMODEL / BNh, NTOK / BMh), 256, GEMM_SMEM>>>(
        yh, wph, out, NTOK, DMODEL, DMODEL);
}